// round 1
// baseline (speedup 1.0000x reference)
#include <cuda_runtime.h>
#include <cuda_bf16.h>

#define N_NODES   50000
#define F_DIM     256
#define N_EDGES   800000
#define PAD_M     50048          // 391 * 128, multiple of GEMM BM

// Scratch: aggregated messages (padded rows are kept zero so GEMM needs no load guards)
__device__ float g_agg[(size_t)PAD_M * F_DIM];

// ---------------------------------------------------------------------------
// Kernel 1: zero the aggregation buffer (float4 stores)
// ---------------------------------------------------------------------------
__global__ void zero_agg_kernel() {
    size_t i = (size_t)blockIdx.x * blockDim.x + threadIdx.x;
    size_t total = (size_t)PAD_M * F_DIM / 4;
    if (i < total) {
        float4 z = make_float4(0.f, 0.f, 0.f, 0.f);
        reinterpret_cast<float4*>(g_agg)[i] = z;
    }
}

// ---------------------------------------------------------------------------
// Kernel 2: SpMM scatter. One warp per edge.
//   agg[row] += val * x[col]   (256 floats = 32 lanes x 2 float4)
// Uses vectorized red.global.add.v4.f32 (sm_90+) — fire-and-forget L2 reduction.
// ---------------------------------------------------------------------------
__global__ void spmm_kernel(const float* __restrict__ x,
                            const int*   __restrict__ edge_row,
                            const int*   __restrict__ edge_col,
                            const float* __restrict__ edge_val) {
    int e    = (blockIdx.x * blockDim.x + threadIdx.x) >> 5;
    int lane = threadIdx.x & 31;
    if (e >= N_EDGES) return;

    int   r = edge_row[e];
    int   c = edge_col[e];
    float v = edge_val[e];

    const float4* xr = reinterpret_cast<const float4*>(x + (size_t)c * F_DIM);
    float4*       ar = reinterpret_cast<float4*>(g_agg + (size_t)r * F_DIM);

#pragma unroll
    for (int j = 0; j < 2; j++) {
        int idx = lane + 32 * j;           // 0..63 float4 slots per row
        float4 xv = xr[idx];
        float mx = v * xv.x, my = v * xv.y, mz = v * xv.z, mw = v * xv.w;
        asm volatile("red.global.add.v4.f32 [%0], {%1, %2, %3, %4};"
                     :: "l"(&ar[idx]), "f"(mx), "f"(my), "f"(mz), "f"(mw)
                     : "memory");
    }
}

// ---------------------------------------------------------------------------
// Kernel 3: SGEMM  out[m, n] = sum_k agg[m, k] * W[n, k] + b[n]
// Tiles: BM=128, BN=64, BK=32. 256 threads, 8x4 micro-tile each.
// A tile stored natural [BM][BK] (float4 stores, broadcast scalar reads);
// W tile stored transposed [BK][BN+4] (float4 reads along N).
// ---------------------------------------------------------------------------
#define BM 128
#define BN 64
#define BK 32
#define BN_PAD (BN + 4)

__global__ void gemm_kernel(const float* __restrict__ Wm,
                            const float* __restrict__ bias,
                            float* __restrict__ out) {
    __shared__ float As[BM][BK];       // 16 KB
    __shared__ float Ws[BK][BN_PAD];   // 8.5 KB

    int t  = threadIdx.x;              // 0..255
    int tx = t & 15;                   // 16 cols of threads -> 4 outputs each
    int ty = t >> 4;                   // 16 rows of threads -> 8 outputs each
    int m0 = blockIdx.x * BM;
    int n0 = blockIdx.y * BN;

    float acc[8][4];
#pragma unroll
    for (int i = 0; i < 8; i++)
#pragma unroll
        for (int j = 0; j < 4; j++) acc[i][j] = 0.f;

    for (int k0 = 0; k0 < F_DIM; k0 += BK) {
        // Load A tile: 128x32 = 1024 float4-slots? -> 128 rows * 8 float4 = 1024, 4/thread
#pragma unroll
        for (int i = 0; i < 4; i++) {
            int idx = t + i * 256;     // 0..1023
            int row = idx >> 3;        // 0..127
            int c4  = idx & 7;         // 0..7
            float4 v = *reinterpret_cast<const float4*>(
                g_agg + (size_t)(m0 + row) * F_DIM + k0 + c4 * 4);
            *reinterpret_cast<float4*>(&As[row][c4 * 4]) = v;
        }
        // Load W tile transposed: 64 rows (n) x 32 (k) = 512 float4-slots, 2/thread
#pragma unroll
        for (int i = 0; i < 2; i++) {
            int idx = t + i * 256;     // 0..511
            int o   = idx >> 3;        // 0..63
            int c4  = idx & 7;         // 0..7
            float4 v = *reinterpret_cast<const float4*>(
                Wm + (size_t)(n0 + o) * F_DIM + k0 + c4 * 4);
            Ws[c4 * 4 + 0][o] = v.x;
            Ws[c4 * 4 + 1][o] = v.y;
            Ws[c4 * 4 + 2][o] = v.z;
            Ws[c4 * 4 + 3][o] = v.w;
        }
        __syncthreads();

#pragma unroll
        for (int k = 0; k < BK; k++) {
            float a[8];
#pragma unroll
            for (int i = 0; i < 8; i++) a[i] = As[ty * 8 + i][k];  // broadcast reads
            float4 w4 = *reinterpret_cast<const float4*>(&Ws[k][tx * 4]);
            float w[4] = {w4.x, w4.y, w4.z, w4.w};
#pragma unroll
            for (int i = 0; i < 8; i++)
#pragma unroll
                for (int j = 0; j < 4; j++)
                    acc[i][j] += a[i] * w[j];
        }
        __syncthreads();
    }

    // Epilogue: add bias, store (guard against padded rows)
    float4 bv = *reinterpret_cast<const float4*>(bias + n0 + tx * 4);
#pragma unroll
    for (int i = 0; i < 8; i++) {
        int m = m0 + ty * 8 + i;
        if (m < N_NODES) {
            float4 o;
            o.x = acc[i][0] + bv.x;
            o.y = acc[i][1] + bv.y;
            o.z = acc[i][2] + bv.z;
            o.w = acc[i][3] + bv.w;
            *reinterpret_cast<float4*>(out + (size_t)m * F_DIM + n0 + tx * 4) = o;
        }
    }
}

// ---------------------------------------------------------------------------
// Launch
// ---------------------------------------------------------------------------
extern "C" void kernel_launch(void* const* d_in, const int* in_sizes, int n_in,
                              void* d_out, int out_size) {
    const float* x        = (const float*)d_in[0];
    const int*   edge_row = (const int*)  d_in[1];
    const int*   edge_col = (const int*)  d_in[2];
    const float* edge_val = (const float*)d_in[3];
    const float* W        = (const float*)d_in[4];
    const float* b        = (const float*)d_in[5];
    float*       out      = (float*)d_out;

    // 1) zero agg (incl. padding rows)
    {
        size_t total = (size_t)PAD_M * F_DIM / 4;
        int blocks = (int)((total + 255) / 256);
        zero_agg_kernel<<<blocks, 256>>>();
    }
    // 2) SpMM scatter: one warp per edge
    {
        long long threads = (long long)N_EDGES * 32;
        int blocks = (int)((threads + 255) / 256);
        spmm_kernel<<<blocks, 256>>>(x, edge_row, edge_col, edge_val);
    }
    // 3) GEMM + bias
    {
        dim3 grid(PAD_M / BM, F_DIM / BN);  // 391 x 4
        gemm_kernel<<<grid, 256>>>(W, b, out);
    }
}

// round 2
// speedup vs baseline: 1.2489x; 1.2489x over previous
#include <cuda_runtime.h>
#include <cuda_bf16.h>
#include <cstdint>

#define N_NODES   50000
#define F_DIM     256
#define N_EDGES   800000
#define PAD_M     50048          // 391 * 128, multiple of GEMM BM

// Scratch: aggregated messages (padded rows stay zero -> GEMM needs no load guards)
__device__ float g_agg[(size_t)PAD_M * F_DIM];

// ---------------------------------------------------------------------------
// Kernel 1: zero the aggregation buffer (float4 stores)
// ---------------------------------------------------------------------------
__global__ void zero_agg_kernel() {
    size_t i = (size_t)blockIdx.x * blockDim.x + threadIdx.x;
    size_t total = (size_t)PAD_M * F_DIM / 4;
    if (i < total) {
        float4 z = make_float4(0.f, 0.f, 0.f, 0.f);
        reinterpret_cast<float4*>(g_agg)[i] = z;
    }
}

// ---------------------------------------------------------------------------
// Kernel 2: SpMM scatter. One warp per edge.
//   agg[row] += val * x[col]   (256 floats = 32 lanes x 2 float4)
// red.global.add.v4.f32: fire-and-forget vectorized L2 reduction.
// ---------------------------------------------------------------------------
__global__ void spmm_kernel(const float* __restrict__ x,
                            const int*   __restrict__ edge_row,
                            const int*   __restrict__ edge_col,
                            const float* __restrict__ edge_val) {
    int e    = (blockIdx.x * blockDim.x + threadIdx.x) >> 5;
    int lane = threadIdx.x & 31;
    if (e >= N_EDGES) return;

    int   r = edge_row[e];
    int   c = edge_col[e];
    float v = edge_val[e];

    const float4* xr = reinterpret_cast<const float4*>(x + (size_t)c * F_DIM);
    float4*       ar = reinterpret_cast<float4*>(g_agg + (size_t)r * F_DIM);

#pragma unroll
    for (int j = 0; j < 2; j++) {
        int idx = lane + 32 * j;           // 0..63 float4 slots per row
        float4 xv = __ldg(&xr[idx]);
        float mx = v * xv.x, my = v * xv.y, mz = v * xv.z, mw = v * xv.w;
        asm volatile("red.global.add.v4.f32 [%0], {%1, %2, %3, %4};"
                     :: "l"(&ar[idx]), "f"(mx), "f"(my), "f"(mz), "f"(mw)
                     : "memory");
    }
}

// ---------------------------------------------------------------------------
// Kernel 3: Tensor-core GEMM  out[m,n] = sum_k agg[m,k] * W[n,k] + b[n]
// Split-bf16 emulated fp32: a = ah + al (bf16 each), b = bh + bl.
//   a*b ~= ah*bh + ah*bl + al*bh   (error ~2^-16 relative)
// mma.sync.aligned.m16n8k16.row.col.f32.bf16.bf16.f32
// CTA tile 128x128, 8 warps in 4(M) x 2(N), warp tile 32x64.
// Smem rows padded to 40 halfs -> fragment LDS bank-conflict-free.
// ---------------------------------------------------------------------------
#define BM 128
#define BN 128
#define BK 32
#define LDS_K 40   // padded row stride in halfs

__device__ __forceinline__ void mma_bf16(float* c, const uint32_t* a, const uint32_t* b) {
    asm volatile(
        "mma.sync.aligned.m16n8k16.row.col.f32.bf16.bf16.f32 "
        "{%0,%1,%2,%3}, {%4,%5,%6,%7}, {%8,%9}, {%0,%1,%2,%3};"
        : "+f"(c[0]), "+f"(c[1]), "+f"(c[2]), "+f"(c[3])
        : "r"(a[0]), "r"(a[1]), "r"(a[2]), "r"(a[3]), "r"(b[0]), "r"(b[1]));
}

__device__ __forceinline__ uint32_t pack_bf16_hi(float x, float y) {
    __nv_bfloat162 h = __floats2bfloat162_rn(x, y);
    return *reinterpret_cast<uint32_t*>(&h);
}

__global__ __launch_bounds__(256, 1)
void gemm_kernel(const float* __restrict__ Wm,
                 const float* __restrict__ bias,
                 float* __restrict__ out) {
    __shared__ __nv_bfloat16 As_hi[BM][LDS_K];
    __shared__ __nv_bfloat16 As_lo[BM][LDS_K];
    __shared__ __nv_bfloat16 Ws_hi[BN][LDS_K];
    __shared__ __nv_bfloat16 Ws_lo[BN][LDS_K];

    const int t    = threadIdx.x;
    const int lane = t & 31;
    const int wid  = t >> 5;          // 0..7
    const int wm   = wid & 3;         // 4 warps along M
    const int wn   = wid >> 2;        // 2 warps along N
    const int g    = lane >> 2;       // group id 0..7
    const int tid4 = lane & 3;        // 0..3

    const int m0 = blockIdx.x * BM;
    const int n0 = blockIdx.y * BN;

    float acc[2][8][4];                // 2 M-atoms x 8 N-atoms x 4 f32
#pragma unroll
    for (int i = 0; i < 2; i++)
#pragma unroll
        for (int j = 0; j < 8; j++)
#pragma unroll
            for (int k = 0; k < 4; k++) acc[i][j][k] = 0.f;

    for (int k0 = 0; k0 < F_DIM; k0 += BK) {
        // ---- stage A tile (128x32 fp32 -> hi/lo bf16), 4 float4 per thread
#pragma unroll
        for (int i = 0; i < 4; i++) {
            int idx = t + i * 256;       // 0..1023
            int row = idx >> 3;          // 0..127
            int c4  = idx & 7;           // 0..7
            float4 v = *reinterpret_cast<const float4*>(
                g_agg + (size_t)(m0 + row) * F_DIM + k0 + c4 * 4);
            uint32_t h0 = pack_bf16_hi(v.x, v.y);
            uint32_t h1 = pack_bf16_hi(v.z, v.w);
            __nv_bfloat162 hb0 = *reinterpret_cast<__nv_bfloat162*>(&h0);
            __nv_bfloat162 hb1 = *reinterpret_cast<__nv_bfloat162*>(&h1);
            uint32_t l0 = pack_bf16_hi(v.x - __bfloat162float(hb0.x),
                                       v.y - __bfloat162float(hb0.y));
            uint32_t l1 = pack_bf16_hi(v.z - __bfloat162float(hb1.x),
                                       v.w - __bfloat162float(hb1.y));
            *reinterpret_cast<uint32_t*>(&As_hi[row][c4 * 4])     = h0;
            *reinterpret_cast<uint32_t*>(&As_hi[row][c4 * 4 + 2]) = h1;
            *reinterpret_cast<uint32_t*>(&As_lo[row][c4 * 4])     = l0;
            *reinterpret_cast<uint32_t*>(&As_lo[row][c4 * 4 + 2]) = l1;
        }
        // ---- stage W tile (128x32 fp32 -> hi/lo bf16), W[n][k] k-major
#pragma unroll
        for (int i = 0; i < 4; i++) {
            int idx = t + i * 256;
            int row = idx >> 3;          // n index 0..127
            int c4  = idx & 7;
            float4 v = *reinterpret_cast<const float4*>(
                Wm + (size_t)(n0 + row) * F_DIM + k0 + c4 * 4);
            uint32_t h0 = pack_bf16_hi(v.x, v.y);
            uint32_t h1 = pack_bf16_hi(v.z, v.w);
            __nv_bfloat162 hb0 = *reinterpret_cast<__nv_bfloat162*>(&h0);
            __nv_bfloat162 hb1 = *reinterpret_cast<__nv_bfloat162*>(&h1);
            uint32_t l0 = pack_bf16_hi(v.x - __bfloat162float(hb0.x),
                                       v.y - __bfloat162float(hb0.y));
            uint32_t l1 = pack_bf16_hi(v.z - __bfloat162float(hb1.x),
                                       v.w - __bfloat162float(hb1.y));
            *reinterpret_cast<uint32_t*>(&Ws_hi[row][c4 * 4])     = h0;
            *reinterpret_cast<uint32_t*>(&Ws_hi[row][c4 * 4 + 2]) = h1;
            *reinterpret_cast<uint32_t*>(&Ws_lo[row][c4 * 4])     = l0;
            *reinterpret_cast<uint32_t*>(&Ws_lo[row][c4 * 4 + 2]) = l1;
        }
        __syncthreads();

        // ---- compute: 2 k-steps of 16 within this 32-chunk
#pragma unroll
        for (int ks = 0; ks < 2; ks++) {
            int kb = ks * 16;
            uint32_t a_hi[2][4], a_lo[2][4];
#pragma unroll
            for (int mi = 0; mi < 2; mi++) {
                int r = wm * 32 + mi * 16;
                a_hi[mi][0] = *reinterpret_cast<const uint32_t*>(&As_hi[r + g    ][kb + 2 * tid4]);
                a_hi[mi][1] = *reinterpret_cast<const uint32_t*>(&As_hi[r + g + 8][kb + 2 * tid4]);
                a_hi[mi][2] = *reinterpret_cast<const uint32_t*>(&As_hi[r + g    ][kb + 2 * tid4 + 8]);
                a_hi[mi][3] = *reinterpret_cast<const uint32_t*>(&As_hi[r + g + 8][kb + 2 * tid4 + 8]);
                a_lo[mi][0] = *reinterpret_cast<const uint32_t*>(&As_lo[r + g    ][kb + 2 * tid4]);
                a_lo[mi][1] = *reinterpret_cast<const uint32_t*>(&As_lo[r + g + 8][kb + 2 * tid4]);
                a_lo[mi][2] = *reinterpret_cast<const uint32_t*>(&As_lo[r + g    ][kb + 2 * tid4 + 8]);
                a_lo[mi][3] = *reinterpret_cast<const uint32_t*>(&As_lo[r + g + 8][kb + 2 * tid4 + 8]);
            }
            uint32_t b_hi[8][2], b_lo[8][2];
#pragma unroll
            for (int ni = 0; ni < 8; ni++) {
                int n = wn * 64 + ni * 8 + g;
                b_hi[ni][0] = *reinterpret_cast<const uint32_t*>(&Ws_hi[n][kb + 2 * tid4]);
                b_hi[ni][1] = *reinterpret_cast<const uint32_t*>(&Ws_hi[n][kb + 2 * tid4 + 8]);
                b_lo[ni][0] = *reinterpret_cast<const uint32_t*>(&Ws_lo[n][kb + 2 * tid4]);
                b_lo[ni][1] = *reinterpret_cast<const uint32_t*>(&Ws_lo[n][kb + 2 * tid4 + 8]);
            }
#pragma unroll
            for (int mi = 0; mi < 2; mi++) {
#pragma unroll
                for (int ni = 0; ni < 8; ni++) {
                    mma_bf16(acc[mi][ni], a_hi[mi], b_hi[ni]);
                    mma_bf16(acc[mi][ni], a_hi[mi], b_lo[ni]);
                    mma_bf16(acc[mi][ni], a_lo[mi], b_hi[ni]);
                }
            }
        }
        __syncthreads();
    }

    // ---- epilogue: bias + store (float2 per acc pair)
#pragma unroll
    for (int mi = 0; mi < 2; mi++) {
        int r_base = m0 + wm * 32 + mi * 16;
#pragma unroll
        for (int ni = 0; ni < 8; ni++) {
            int col = n0 + wn * 64 + ni * 8 + 2 * tid4;
            float2 bv = *reinterpret_cast<const float2*>(bias + col);
            int r0 = r_base + g;
            int r1 = r_base + g + 8;
            if (r0 < N_NODES) {
                float2 o = make_float2(acc[mi][ni][0] + bv.x, acc[mi][ni][1] + bv.y);
                *reinterpret_cast<float2*>(out + (size_t)r0 * F_DIM + col) = o;
            }
            if (r1 < N_NODES) {
                float2 o = make_float2(acc[mi][ni][2] + bv.x, acc[mi][ni][3] + bv.y);
                *reinterpret_cast<float2*>(out + (size_t)r1 * F_DIM + col) = o;
            }
        }
    }
}

// ---------------------------------------------------------------------------
// Launch
// ---------------------------------------------------------------------------
extern "C" void kernel_launch(void* const* d_in, const int* in_sizes, int n_in,
                              void* d_out, int out_size) {
    const float* x        = (const float*)d_in[0];
    const int*   edge_row = (const int*)  d_in[1];
    const int*   edge_col = (const int*)  d_in[2];
    const float* edge_val = (const float*)d_in[3];
    const float* W        = (const float*)d_in[4];
    const float* b        = (const float*)d_in[5];
    float*       out      = (float*)d_out;

    // 1) zero agg (incl. padding rows)
    {
        size_t total = (size_t)PAD_M * F_DIM / 4;
        int blocks = (int)((total + 255) / 256);
        zero_agg_kernel<<<blocks, 256>>>();
    }
    // 2) SpMM scatter: one warp per edge
    {
        long long threads = (long long)N_EDGES * 32;
        int blocks = (int)((threads + 255) / 256);
        spmm_kernel<<<blocks, 256>>>(x, edge_row, edge_col, edge_val);
    }
    // 3) Tensor-core GEMM + bias
    {
        dim3 grid(PAD_M / BM, F_DIM / BN);  // 391 x 2
        gemm_kernel<<<grid, 256>>>(W, b, out);
    }
}

// round 3
// speedup vs baseline: 1.6387x; 1.3121x over previous
#include <cuda_runtime.h>
#include <cuda_bf16.h>
#include <cstdint>

#define N_NODES   50000
#define F_DIM     256
#define N_EDGES   800000
#define PAD_M     50048          // 391 * 128, multiple of GEMM BM

#define SCAN_B    256
#define SCAN_NB   ((N_NODES + SCAN_B - 1) / SCAN_B)   // 196

// Scratch buffers (__device__ globals: no allocation allowed)
__device__ float g_agg[(size_t)PAD_M * F_DIM];
__device__ int   g_cnt[N_NODES];          // per-row degree
__device__ int   g_off[N_NODES + 1];      // CSR row offsets
__device__ int   g_pos[N_NODES];          // running scatter cursor
__device__ int   g_bsum[SCAN_NB];         // block sums for scan
__device__ int   g_boff[SCAN_NB];         // scanned block offsets
__device__ int   g_col_s[N_EDGES];        // CSR col indices
__device__ float g_val_s[N_EDGES];        // CSR values

// ---------------------------------------------------------------------------
// CSR build
// ---------------------------------------------------------------------------
__global__ void k_zero_cnt() {
    int i = blockIdx.x * blockDim.x + threadIdx.x;
    if (i < N_NODES) g_cnt[i] = 0;
}

__global__ void k_hist(const int* __restrict__ edge_row) {
    int e = blockIdx.x * blockDim.x + threadIdx.x;
    if (e < N_EDGES) atomicAdd(&g_cnt[edge_row[e]], 1);
}

// per-block inclusive scan -> exclusive output + block totals
__global__ void k_scan1() {
    __shared__ int s[SCAN_B];
    int i = blockIdx.x * SCAN_B + threadIdx.x;
    int v = (i < N_NODES) ? g_cnt[i] : 0;
    s[threadIdx.x] = v;
    __syncthreads();
    int acc = v;
#pragma unroll
    for (int d = 1; d < SCAN_B; d <<= 1) {
        int t = (threadIdx.x >= d) ? s[threadIdx.x - d] : 0;
        __syncthreads();
        acc += t;
        s[threadIdx.x] = acc;
        __syncthreads();
    }
    if (i < N_NODES) g_off[i] = acc - v;            // exclusive, block-local
    if (threadIdx.x == SCAN_B - 1) g_bsum[blockIdx.x] = acc;
}

__global__ void k_scan2() {                          // single block
    __shared__ int s[SCAN_B];
    int v = (threadIdx.x < SCAN_NB) ? g_bsum[threadIdx.x] : 0;
    s[threadIdx.x] = v;
    __syncthreads();
    int acc = v;
#pragma unroll
    for (int d = 1; d < SCAN_B; d <<= 1) {
        int t = (threadIdx.x >= d) ? s[threadIdx.x - d] : 0;
        __syncthreads();
        acc += t;
        s[threadIdx.x] = acc;
        __syncthreads();
    }
    if (threadIdx.x < SCAN_NB) g_boff[threadIdx.x] = acc - v;   // exclusive
}

__global__ void k_scan3() {
    int i = blockIdx.x * SCAN_B + threadIdx.x;
    if (i < N_NODES) {
        int o = g_off[i] + g_boff[blockIdx.x];
        g_off[i] = o;
        g_pos[i] = o;
    }
    if (i == 0) g_off[N_NODES] = N_EDGES;
}

__global__ void k_scatter(const int*   __restrict__ edge_row,
                          const int*   __restrict__ edge_col,
                          const float* __restrict__ edge_val) {
    int e = blockIdx.x * blockDim.x + threadIdx.x;
    if (e < N_EDGES) {
        int r = edge_row[e];
        int p = atomicAdd(&g_pos[r], 1);
        g_col_s[p] = edge_col[e];
        g_val_s[p] = edge_val[e];
    }
}

// ---------------------------------------------------------------------------
// SpMM gather: one warp per row. acc[i] = sum_e val_e * x[col_e]
// Lane covers float4 slots {lane, lane+32} of the 64-slot row.
// Rows >= N_NODES (padding) get zeros, so the GEMM needs no guards.
// ---------------------------------------------------------------------------
__global__ __launch_bounds__(256)
void k_gather(const float* __restrict__ x) {
    int r    = (blockIdx.x * blockDim.x + threadIdx.x) >> 5;
    int lane = threadIdx.x & 31;
    if (r >= PAD_M) return;

    float4 acc0 = make_float4(0.f, 0.f, 0.f, 0.f);
    float4 acc1 = make_float4(0.f, 0.f, 0.f, 0.f);

    if (r < N_NODES) {
        int start = g_off[r];
        int end   = g_off[r + 1];

        for (int base = start; base < end; base += 32) {
            int n = min(32, end - base);
            int   col = 0;
            float val = 0.f;
            if (lane < n) {
                col = g_col_s[base + lane];
                val = g_val_s[base + lane];
            }
            int j = 0;
            // 4-edge software pipeline: 8 independent LDG.128 in flight
            for (; j + 4 <= n; j += 4) {
                int   c0 = __shfl_sync(0xffffffffu, col, j);
                int   c1 = __shfl_sync(0xffffffffu, col, j + 1);
                int   c2 = __shfl_sync(0xffffffffu, col, j + 2);
                int   c3 = __shfl_sync(0xffffffffu, col, j + 3);
                float v0 = __shfl_sync(0xffffffffu, val, j);
                float v1 = __shfl_sync(0xffffffffu, val, j + 1);
                float v2 = __shfl_sync(0xffffffffu, val, j + 2);
                float v3 = __shfl_sync(0xffffffffu, val, j + 3);
                const float4* p0 = reinterpret_cast<const float4*>(x + (size_t)c0 * F_DIM);
                const float4* p1 = reinterpret_cast<const float4*>(x + (size_t)c1 * F_DIM);
                const float4* p2 = reinterpret_cast<const float4*>(x + (size_t)c2 * F_DIM);
                const float4* p3 = reinterpret_cast<const float4*>(x + (size_t)c3 * F_DIM);
                float4 a0 = __ldg(&p0[lane]);      float4 b0 = __ldg(&p0[lane + 32]);
                float4 a1 = __ldg(&p1[lane]);      float4 b1 = __ldg(&p1[lane + 32]);
                float4 a2 = __ldg(&p2[lane]);      float4 b2 = __ldg(&p2[lane + 32]);
                float4 a3 = __ldg(&p3[lane]);      float4 b3 = __ldg(&p3[lane + 32]);
                acc0.x += v0 * a0.x; acc0.y += v0 * a0.y; acc0.z += v0 * a0.z; acc0.w += v0 * a0.w;
                acc1.x += v0 * b0.x; acc1.y += v0 * b0.y; acc1.z += v0 * b0.z; acc1.w += v0 * b0.w;
                acc0.x += v1 * a1.x; acc0.y += v1 * a1.y; acc0.z += v1 * a1.z; acc0.w += v1 * a1.w;
                acc1.x += v1 * b1.x; acc1.y += v1 * b1.y; acc1.z += v1 * b1.z; acc1.w += v1 * b1.w;
                acc0.x += v2 * a2.x; acc0.y += v2 * a2.y; acc0.z += v2 * a2.z; acc0.w += v2 * a2.w;
                acc1.x += v2 * b2.x; acc1.y += v2 * b2.y; acc1.z += v2 * b2.z; acc1.w += v2 * b2.w;
                acc0.x += v3 * a3.x; acc0.y += v3 * a3.y; acc0.z += v3 * a3.z; acc0.w += v3 * a3.w;
                acc1.x += v3 * b3.x; acc1.y += v3 * b3.y; acc1.z += v3 * b3.z; acc1.w += v3 * b3.w;
            }
            for (; j < n; j++) {
                int   c = __shfl_sync(0xffffffffu, col, j);
                float v = __shfl_sync(0xffffffffu, val, j);
                const float4* p = reinterpret_cast<const float4*>(x + (size_t)c * F_DIM);
                float4 a = __ldg(&p[lane]);
                float4 bb = __ldg(&p[lane + 32]);
                acc0.x += v * a.x;  acc0.y += v * a.y;  acc0.z += v * a.z;  acc0.w += v * a.w;
                acc1.x += v * bb.x; acc1.y += v * bb.y; acc1.z += v * bb.z; acc1.w += v * bb.w;
            }
        }
    }

    float4* ar = reinterpret_cast<float4*>(g_agg + (size_t)r * F_DIM);
    ar[lane]      = acc0;
    ar[lane + 32] = acc1;
}

// ---------------------------------------------------------------------------
// Tensor-core GEMM  out[m,n] = sum_k agg[m,k] * W[n,k] + b[n]
// Split-bf16 emulated fp32 (3 MMAs), CTA 128x128, 8 warps 4(M)x2(N).
// ---------------------------------------------------------------------------
#define BM 128
#define BN 128
#define BK 32
#define LDS_K 40

__device__ __forceinline__ void mma_bf16(float* c, const uint32_t* a, const uint32_t* b) {
    asm volatile(
        "mma.sync.aligned.m16n8k16.row.col.f32.bf16.bf16.f32 "
        "{%0,%1,%2,%3}, {%4,%5,%6,%7}, {%8,%9}, {%0,%1,%2,%3};"
        : "+f"(c[0]), "+f"(c[1]), "+f"(c[2]), "+f"(c[3])
        : "r"(a[0]), "r"(a[1]), "r"(a[2]), "r"(a[3]), "r"(b[0]), "r"(b[1]));
}

__device__ __forceinline__ uint32_t pack_bf16_hi(float x, float y) {
    __nv_bfloat162 h = __floats2bfloat162_rn(x, y);
    return *reinterpret_cast<uint32_t*>(&h);
}

__global__ __launch_bounds__(256, 1)
void gemm_kernel(const float* __restrict__ Wm,
                 const float* __restrict__ bias,
                 float* __restrict__ out) {
    __shared__ __nv_bfloat16 As_hi[BM][LDS_K];
    __shared__ __nv_bfloat16 As_lo[BM][LDS_K];
    __shared__ __nv_bfloat16 Ws_hi[BN][LDS_K];
    __shared__ __nv_bfloat16 Ws_lo[BN][LDS_K];

    const int t    = threadIdx.x;
    const int lane = t & 31;
    const int wid  = t >> 5;
    const int wm   = wid & 3;
    const int wn   = wid >> 2;
    const int g    = lane >> 2;
    const int tid4 = lane & 3;

    const int m0 = blockIdx.x * BM;
    const int n0 = blockIdx.y * BN;

    float acc[2][8][4];
#pragma unroll
    for (int i = 0; i < 2; i++)
#pragma unroll
        for (int j = 0; j < 8; j++)
#pragma unroll
            for (int k = 0; k < 4; k++) acc[i][j][k] = 0.f;

    for (int k0 = 0; k0 < F_DIM; k0 += BK) {
#pragma unroll
        for (int i = 0; i < 4; i++) {
            int idx = t + i * 256;
            int row = idx >> 3;
            int c4  = idx & 7;
            float4 v = *reinterpret_cast<const float4*>(
                g_agg + (size_t)(m0 + row) * F_DIM + k0 + c4 * 4);
            uint32_t h0 = pack_bf16_hi(v.x, v.y);
            uint32_t h1 = pack_bf16_hi(v.z, v.w);
            __nv_bfloat162 hb0 = *reinterpret_cast<__nv_bfloat162*>(&h0);
            __nv_bfloat162 hb1 = *reinterpret_cast<__nv_bfloat162*>(&h1);
            uint32_t l0 = pack_bf16_hi(v.x - __bfloat162float(hb0.x),
                                       v.y - __bfloat162float(hb0.y));
            uint32_t l1 = pack_bf16_hi(v.z - __bfloat162float(hb1.x),
                                       v.w - __bfloat162float(hb1.y));
            *reinterpret_cast<uint32_t*>(&As_hi[row][c4 * 4])     = h0;
            *reinterpret_cast<uint32_t*>(&As_hi[row][c4 * 4 + 2]) = h1;
            *reinterpret_cast<uint32_t*>(&As_lo[row][c4 * 4])     = l0;
            *reinterpret_cast<uint32_t*>(&As_lo[row][c4 * 4 + 2]) = l1;
        }
#pragma unroll
        for (int i = 0; i < 4; i++) {
            int idx = t + i * 256;
            int row = idx >> 3;
            int c4  = idx & 7;
            float4 v = *reinterpret_cast<const float4*>(
                Wm + (size_t)(n0 + row) * F_DIM + k0 + c4 * 4);
            uint32_t h0 = pack_bf16_hi(v.x, v.y);
            uint32_t h1 = pack_bf16_hi(v.z, v.w);
            __nv_bfloat162 hb0 = *reinterpret_cast<__nv_bfloat162*>(&h0);
            __nv_bfloat162 hb1 = *reinterpret_cast<__nv_bfloat162*>(&h1);
            uint32_t l0 = pack_bf16_hi(v.x - __bfloat162float(hb0.x),
                                       v.y - __bfloat162float(hb0.y));
            uint32_t l1 = pack_bf16_hi(v.z - __bfloat162float(hb1.x),
                                       v.w - __bfloat162float(hb1.y));
            *reinterpret_cast<uint32_t*>(&Ws_hi[row][c4 * 4])     = h0;
            *reinterpret_cast<uint32_t*>(&Ws_hi[row][c4 * 4 + 2]) = h1;
            *reinterpret_cast<uint32_t*>(&Ws_lo[row][c4 * 4])     = l0;
            *reinterpret_cast<uint32_t*>(&Ws_lo[row][c4 * 4 + 2]) = l1;
        }
        __syncthreads();

#pragma unroll
        for (int ks = 0; ks < 2; ks++) {
            int kb = ks * 16;
            uint32_t a_hi[2][4], a_lo[2][4];
#pragma unroll
            for (int mi = 0; mi < 2; mi++) {
                int r = wm * 32 + mi * 16;
                a_hi[mi][0] = *reinterpret_cast<const uint32_t*>(&As_hi[r + g    ][kb + 2 * tid4]);
                a_hi[mi][1] = *reinterpret_cast<const uint32_t*>(&As_hi[r + g + 8][kb + 2 * tid4]);
                a_hi[mi][2] = *reinterpret_cast<const uint32_t*>(&As_hi[r + g    ][kb + 2 * tid4 + 8]);
                a_hi[mi][3] = *reinterpret_cast<const uint32_t*>(&As_hi[r + g + 8][kb + 2 * tid4 + 8]);
                a_lo[mi][0] = *reinterpret_cast<const uint32_t*>(&As_lo[r + g    ][kb + 2 * tid4]);
                a_lo[mi][1] = *reinterpret_cast<const uint32_t*>(&As_lo[r + g + 8][kb + 2 * tid4]);
                a_lo[mi][2] = *reinterpret_cast<const uint32_t*>(&As_lo[r + g    ][kb + 2 * tid4 + 8]);
                a_lo[mi][3] = *reinterpret_cast<const uint32_t*>(&As_lo[r + g + 8][kb + 2 * tid4 + 8]);
            }
            uint32_t b_hi[8][2], b_lo[8][2];
#pragma unroll
            for (int ni = 0; ni < 8; ni++) {
                int n = wn * 64 + ni * 8 + g;
                b_hi[ni][0] = *reinterpret_cast<const uint32_t*>(&Ws_hi[n][kb + 2 * tid4]);
                b_hi[ni][1] = *reinterpret_cast<const uint32_t*>(&Ws_hi[n][kb + 2 * tid4 + 8]);
                b_lo[ni][0] = *reinterpret_cast<const uint32_t*>(&Ws_lo[n][kb + 2 * tid4]);
                b_lo[ni][1] = *reinterpret_cast<const uint32_t*>(&Ws_lo[n][kb + 2 * tid4 + 8]);
            }
#pragma unroll
            for (int mi = 0; mi < 2; mi++) {
#pragma unroll
                for (int ni = 0; ni < 8; ni++) {
                    mma_bf16(acc[mi][ni], a_hi[mi], b_hi[ni]);
                    mma_bf16(acc[mi][ni], a_hi[mi], b_lo[ni]);
                    mma_bf16(acc[mi][ni], a_lo[mi], b_hi[ni]);
                }
            }
        }
        __syncthreads();
    }

#pragma unroll
    for (int mi = 0; mi < 2; mi++) {
        int r_base = m0 + wm * 32 + mi * 16;
#pragma unroll
        for (int ni = 0; ni < 8; ni++) {
            int col = n0 + wn * 64 + ni * 8 + 2 * tid4;
            float2 bv = *reinterpret_cast<const float2*>(bias + col);
            int r0 = r_base + g;
            int r1 = r_base + g + 8;
            if (r0 < N_NODES) {
                float2 o = make_float2(acc[mi][ni][0] + bv.x, acc[mi][ni][1] + bv.y);
                *reinterpret_cast<float2*>(out + (size_t)r0 * F_DIM + col) = o;
            }
            if (r1 < N_NODES) {
                float2 o = make_float2(acc[mi][ni][2] + bv.x, acc[mi][ni][3] + bv.y);
                *reinterpret_cast<float2*>(out + (size_t)r1 * F_DIM + col) = o;
            }
        }
    }
}

// ---------------------------------------------------------------------------
// Launch
// ---------------------------------------------------------------------------
extern "C" void kernel_launch(void* const* d_in, const int* in_sizes, int n_in,
                              void* d_out, int out_size) {
    const float* x        = (const float*)d_in[0];
    const int*   edge_row = (const int*)  d_in[1];
    const int*   edge_col = (const int*)  d_in[2];
    const float* edge_val = (const float*)d_in[3];
    const float* W        = (const float*)d_in[4];
    const float* b        = (const float*)d_in[5];
    float*       out      = (float*)d_out;

    // CSR build
    k_zero_cnt<<<SCAN_NB, SCAN_B>>>();
    k_hist<<<(N_EDGES + 255) / 256, 256>>>(edge_row);
    k_scan1<<<SCAN_NB, SCAN_B>>>();
    k_scan2<<<1, SCAN_B>>>();
    k_scan3<<<SCAN_NB, SCAN_B>>>();
    k_scatter<<<(N_EDGES + 255) / 256, 256>>>(edge_row, edge_col, edge_val);

    // SpMM gather (writes all PAD_M rows; padding rows -> zeros)
    k_gather<<<PAD_M / 8, 256>>>(x);

    // Tensor-core GEMM + bias
    dim3 grid(PAD_M / BM, F_DIM / BN);   // 391 x 2
    gemm_kernel<<<grid, 256>>>(W, b, out);
}

// round 4
// speedup vs baseline: 1.6504x; 1.0072x over previous
#include <cuda_runtime.h>
#include <cuda_bf16.h>
#include <cstdint>

#define N_NODES   50000
#define F_DIM     256
#define N_EDGES   800000
#define PAD_M     50048          // 391 * 128

#define SCAN_B    256
#define SCAN_NB   ((N_NODES + SCAN_B - 1) / SCAN_B)   // 196

// Scratch (__device__ globals; no allocation allowed)
__device__ float          g_y[(size_t)N_NODES * F_DIM];   // Y = X @ W^T
__device__ __nv_bfloat16  g_w_hi[F_DIM * F_DIM];          // W split hi
__device__ __nv_bfloat16  g_w_lo[F_DIM * F_DIM];          // W split lo
__device__ int   g_cnt[N_NODES];
__device__ int   g_off[N_NODES + 1];
__device__ int   g_pos[N_NODES];
__device__ int   g_bsum[SCAN_NB];
__device__ int   g_boff[SCAN_NB];
__device__ int   g_col_s[N_EDGES];
__device__ float g_val_s[N_EDGES];

// ---------------------------------------------------------------------------
// W -> (hi, lo) bf16 split, once per call
// ---------------------------------------------------------------------------
__device__ __forceinline__ uint32_t pack_bf16_hi(float x, float y) {
    __nv_bfloat162 h = __floats2bfloat162_rn(x, y);
    return *reinterpret_cast<uint32_t*>(&h);
}

__global__ void k_prep_w(const float* __restrict__ W) {
    int i = blockIdx.x * blockDim.x + threadIdx.x;   // float4 index, 16384 total
    float4 v = reinterpret_cast<const float4*>(W)[i];
    uint32_t h0 = pack_bf16_hi(v.x, v.y);
    uint32_t h1 = pack_bf16_hi(v.z, v.w);
    __nv_bfloat162 hb0 = *reinterpret_cast<__nv_bfloat162*>(&h0);
    __nv_bfloat162 hb1 = *reinterpret_cast<__nv_bfloat162*>(&h1);
    uint32_t l0 = pack_bf16_hi(v.x - __bfloat162float(hb0.x),
                               v.y - __bfloat162float(hb0.y));
    uint32_t l1 = pack_bf16_hi(v.z - __bfloat162float(hb1.x),
                               v.w - __bfloat162float(hb1.y));
    uint32_t* whi = reinterpret_cast<uint32_t*>(g_w_hi);
    uint32_t* wlo = reinterpret_cast<uint32_t*>(g_w_lo);
    whi[2 * i]     = h0;
    whi[2 * i + 1] = h1;
    wlo[2 * i]     = l0;
    wlo[2 * i + 1] = l1;
}

// ---------------------------------------------------------------------------
// CSR build
// ---------------------------------------------------------------------------
__global__ void k_hist(const int* __restrict__ edge_row) {
    int e = blockIdx.x * blockDim.x + threadIdx.x;
    if (e < N_EDGES) atomicAdd(&g_cnt[edge_row[e]], 1);
}

__global__ void k_scan1() {
    __shared__ int s[SCAN_B];
    int i = blockIdx.x * SCAN_B + threadIdx.x;
    int v = (i < N_NODES) ? g_cnt[i] : 0;
    s[threadIdx.x] = v;
    __syncthreads();
    int acc = v;
#pragma unroll
    for (int d = 1; d < SCAN_B; d <<= 1) {
        int t = (threadIdx.x >= d) ? s[threadIdx.x - d] : 0;
        __syncthreads();
        acc += t;
        s[threadIdx.x] = acc;
        __syncthreads();
    }
    if (i < N_NODES) g_off[i] = acc - v;
    if (threadIdx.x == SCAN_B - 1) g_bsum[blockIdx.x] = acc;
}

__global__ void k_scan2() {
    __shared__ int s[SCAN_B];
    int v = (threadIdx.x < SCAN_NB) ? g_bsum[threadIdx.x] : 0;
    s[threadIdx.x] = v;
    __syncthreads();
    int acc = v;
#pragma unroll
    for (int d = 1; d < SCAN_B; d <<= 1) {
        int t = (threadIdx.x >= d) ? s[threadIdx.x - d] : 0;
        __syncthreads();
        acc += t;
        s[threadIdx.x] = acc;
        __syncthreads();
    }
    if (threadIdx.x < SCAN_NB) g_boff[threadIdx.x] = acc - v;
}

__global__ void k_scan3() {
    int i = blockIdx.x * SCAN_B + threadIdx.x;
    if (i < N_NODES) {
        int o = g_off[i] + g_boff[blockIdx.x];
        g_off[i] = o;
        g_pos[i] = o;
    }
    if (i == 0) g_off[N_NODES] = N_EDGES;
}

__global__ void k_scatter(const int*   __restrict__ edge_row,
                          const int*   __restrict__ edge_col,
                          const float* __restrict__ edge_val) {
    int e = blockIdx.x * blockDim.x + threadIdx.x;
    if (e < N_EDGES) {
        int r = edge_row[e];
        int p = atomicAdd(&g_pos[r], 1);
        g_col_s[p] = edge_col[e];
        g_val_s[p] = edge_val[e];
    }
}

// ---------------------------------------------------------------------------
// GEMM  Y[m,n] = sum_k X[m,k] * W[n,k]   (split-bf16 emulated fp32, 3 MMAs)
// CTA 128x128, 8 warps 4(M) x 2(N). W tiles loaded pre-split (bf16 copies).
// ---------------------------------------------------------------------------
#define BM 128
#define BN 128
#define BK 32
#define LDS_K 40

__device__ __forceinline__ void mma_bf16(float* c, const uint32_t* a, const uint32_t* b) {
    asm volatile(
        "mma.sync.aligned.m16n8k16.row.col.f32.bf16.bf16.f32 "
        "{%0,%1,%2,%3}, {%4,%5,%6,%7}, {%8,%9}, {%0,%1,%2,%3};"
        : "+f"(c[0]), "+f"(c[1]), "+f"(c[2]), "+f"(c[3])
        : "r"(a[0]), "r"(a[1]), "r"(a[2]), "r"(a[3]), "r"(b[0]), "r"(b[1]));
}

__global__ __launch_bounds__(256, 1)
void gemm_kernel(const float* __restrict__ X) {
    __shared__ __nv_bfloat16 As_hi[BM][LDS_K];
    __shared__ __nv_bfloat16 As_lo[BM][LDS_K];
    __shared__ __nv_bfloat16 Ws_hi[BN][LDS_K];
    __shared__ __nv_bfloat16 Ws_lo[BN][LDS_K];

    const int t    = threadIdx.x;
    const int lane = t & 31;
    const int wid  = t >> 5;
    const int wm   = wid & 3;
    const int wn   = wid >> 2;
    const int g    = lane >> 2;
    const int tid4 = lane & 3;

    const int m0 = blockIdx.x * BM;
    const int n0 = blockIdx.y * BN;

    float acc[2][8][4];
#pragma unroll
    for (int i = 0; i < 2; i++)
#pragma unroll
        for (int j = 0; j < 8; j++)
#pragma unroll
            for (int k = 0; k < 4; k++) acc[i][j][k] = 0.f;

    for (int k0 = 0; k0 < F_DIM; k0 += BK) {
        // ---- stage X tile (fp32 -> hi/lo), guarded against rows >= N_NODES
#pragma unroll
        for (int i = 0; i < 4; i++) {
            int idx = t + i * 256;
            int row = idx >> 3;
            int c4  = idx & 7;
            int m   = m0 + row;
            float4 v = make_float4(0.f, 0.f, 0.f, 0.f);
            if (m < N_NODES)
                v = *reinterpret_cast<const float4*>(X + (size_t)m * F_DIM + k0 + c4 * 4);
            uint32_t h0 = pack_bf16_hi(v.x, v.y);
            uint32_t h1 = pack_bf16_hi(v.z, v.w);
            __nv_bfloat162 hb0 = *reinterpret_cast<__nv_bfloat162*>(&h0);
            __nv_bfloat162 hb1 = *reinterpret_cast<__nv_bfloat162*>(&h1);
            uint32_t l0 = pack_bf16_hi(v.x - __bfloat162float(hb0.x),
                                       v.y - __bfloat162float(hb0.y));
            uint32_t l1 = pack_bf16_hi(v.z - __bfloat162float(hb1.x),
                                       v.w - __bfloat162float(hb1.y));
            *reinterpret_cast<uint32_t*>(&As_hi[row][c4 * 4])     = h0;
            *reinterpret_cast<uint32_t*>(&As_hi[row][c4 * 4 + 2]) = h1;
            *reinterpret_cast<uint32_t*>(&As_lo[row][c4 * 4])     = l0;
            *reinterpret_cast<uint32_t*>(&As_lo[row][c4 * 4 + 2]) = l1;
        }
        // ---- stage W tile: straight 16B copies of pre-split bf16
#pragma unroll
        for (int i = 0; i < 2; i++) {
            int idx = t + i * 256;          // 0..511
            int row = idx >> 2;             // 0..127
            int c8  = idx & 3;              // 0..3 (chunks of 8 halfs)
            size_t goff = (size_t)(n0 + row) * F_DIM + k0 + c8 * 8;
            uint4 vh = *reinterpret_cast<const uint4*>(g_w_hi + goff);
            uint4 vl = *reinterpret_cast<const uint4*>(g_w_lo + goff);
            *reinterpret_cast<uint4*>(&Ws_hi[row][c8 * 8]) = vh;
            *reinterpret_cast<uint4*>(&Ws_lo[row][c8 * 8]) = vl;
        }
        __syncthreads();

#pragma unroll
        for (int ks = 0; ks < 2; ks++) {
            int kb = ks * 16;
            uint32_t a_hi[2][4], a_lo[2][4];
#pragma unroll
            for (int mi = 0; mi < 2; mi++) {
                int r = wm * 32 + mi * 16;
                a_hi[mi][0] = *reinterpret_cast<const uint32_t*>(&As_hi[r + g    ][kb + 2 * tid4]);
                a_hi[mi][1] = *reinterpret_cast<const uint32_t*>(&As_hi[r + g + 8][kb + 2 * tid4]);
                a_hi[mi][2] = *reinterpret_cast<const uint32_t*>(&As_hi[r + g    ][kb + 2 * tid4 + 8]);
                a_hi[mi][3] = *reinterpret_cast<const uint32_t*>(&As_hi[r + g + 8][kb + 2 * tid4 + 8]);
                a_lo[mi][0] = *reinterpret_cast<const uint32_t*>(&As_lo[r + g    ][kb + 2 * tid4]);
                a_lo[mi][1] = *reinterpret_cast<const uint32_t*>(&As_lo[r + g + 8][kb + 2 * tid4]);
                a_lo[mi][2] = *reinterpret_cast<const uint32_t*>(&As_lo[r + g    ][kb + 2 * tid4 + 8]);
                a_lo[mi][3] = *reinterpret_cast<const uint32_t*>(&As_lo[r + g + 8][kb + 2 * tid4 + 8]);
            }
            uint32_t b_hi[8][2], b_lo[8][2];
#pragma unroll
            for (int ni = 0; ni < 8; ni++) {
                int n = wn * 64 + ni * 8 + g;
                b_hi[ni][0] = *reinterpret_cast<const uint32_t*>(&Ws_hi[n][kb + 2 * tid4]);
                b_hi[ni][1] = *reinterpret_cast<const uint32_t*>(&Ws_hi[n][kb + 2 * tid4 + 8]);
                b_lo[ni][0] = *reinterpret_cast<const uint32_t*>(&Ws_lo[n][kb + 2 * tid4]);
                b_lo[ni][1] = *reinterpret_cast<const uint32_t*>(&Ws_lo[n][kb + 2 * tid4 + 8]);
            }
#pragma unroll
            for (int mi = 0; mi < 2; mi++) {
#pragma unroll
                for (int ni = 0; ni < 8; ni++) {
                    mma_bf16(acc[mi][ni], a_hi[mi], b_hi[ni]);
                    mma_bf16(acc[mi][ni], a_hi[mi], b_lo[ni]);
                    mma_bf16(acc[mi][ni], a_lo[mi], b_hi[ni]);
                }
            }
        }
        __syncthreads();
    }

    // ---- store Y (no bias here)
#pragma unroll
    for (int mi = 0; mi < 2; mi++) {
        int r_base = m0 + wm * 32 + mi * 16;
#pragma unroll
        for (int ni = 0; ni < 8; ni++) {
            int col = n0 + wn * 64 + ni * 8 + 2 * tid4;
            int r0 = r_base + g;
            int r1 = r_base + g + 8;
            if (r0 < N_NODES) {
                float2 o = make_float2(acc[mi][ni][0], acc[mi][ni][1]);
                *reinterpret_cast<float2*>(g_y + (size_t)r0 * F_DIM + col) = o;
            }
            if (r1 < N_NODES) {
                float2 o = make_float2(acc[mi][ni][2], acc[mi][ni][3]);
                *reinterpret_cast<float2*>(g_y + (size_t)r1 * F_DIM + col) = o;
            }
        }
    }
}

// ---------------------------------------------------------------------------
// Gather: out[r] = sum_e val_e * Y[col_e] + b.  One warp per row.
// ---------------------------------------------------------------------------
__global__ __launch_bounds__(256)
void k_gather(const float* __restrict__ bias, float* __restrict__ out) {
    int r    = (blockIdx.x * blockDim.x + threadIdx.x) >> 5;
    int lane = threadIdx.x & 31;
    if (r >= N_NODES) return;

    float4 acc0 = make_float4(0.f, 0.f, 0.f, 0.f);
    float4 acc1 = make_float4(0.f, 0.f, 0.f, 0.f);

    int start = g_off[r];
    int end   = g_off[r + 1];

    for (int base = start; base < end; base += 32) {
        int n = min(32, end - base);
        int   col = 0;
        float val = 0.f;
        if (lane < n) {
            col = g_col_s[base + lane];
            val = g_val_s[base + lane];
        }
        int j = 0;
        for (; j + 4 <= n; j += 4) {
            int   c0 = __shfl_sync(0xffffffffu, col, j);
            int   c1 = __shfl_sync(0xffffffffu, col, j + 1);
            int   c2 = __shfl_sync(0xffffffffu, col, j + 2);
            int   c3 = __shfl_sync(0xffffffffu, col, j + 3);
            float v0 = __shfl_sync(0xffffffffu, val, j);
            float v1 = __shfl_sync(0xffffffffu, val, j + 1);
            float v2 = __shfl_sync(0xffffffffu, val, j + 2);
            float v3 = __shfl_sync(0xffffffffu, val, j + 3);
            const float4* p0 = reinterpret_cast<const float4*>(g_y + (size_t)c0 * F_DIM);
            const float4* p1 = reinterpret_cast<const float4*>(g_y + (size_t)c1 * F_DIM);
            const float4* p2 = reinterpret_cast<const float4*>(g_y + (size_t)c2 * F_DIM);
            const float4* p3 = reinterpret_cast<const float4*>(g_y + (size_t)c3 * F_DIM);
            float4 a0 = __ldg(&p0[lane]);      float4 b0 = __ldg(&p0[lane + 32]);
            float4 a1 = __ldg(&p1[lane]);      float4 b1 = __ldg(&p1[lane + 32]);
            float4 a2 = __ldg(&p2[lane]);      float4 b2 = __ldg(&p2[lane + 32]);
            float4 a3 = __ldg(&p3[lane]);      float4 b3 = __ldg(&p3[lane + 32]);
            acc0.x += v0 * a0.x; acc0.y += v0 * a0.y; acc0.z += v0 * a0.z; acc0.w += v0 * a0.w;
            acc1.x += v0 * b0.x; acc1.y += v0 * b0.y; acc1.z += v0 * b0.z; acc1.w += v0 * b0.w;
            acc0.x += v1 * a1.x; acc0.y += v1 * a1.y; acc0.z += v1 * a1.z; acc0.w += v1 * a1.w;
            acc1.x += v1 * b1.x; acc1.y += v1 * b1.y; acc1.z += v1 * b1.z; acc1.w += v1 * b1.w;
            acc0.x += v2 * a2.x; acc0.y += v2 * a2.y; acc0.z += v2 * a2.z; acc0.w += v2 * a2.w;
            acc1.x += v2 * b2.x; acc1.y += v2 * b2.y; acc1.z += v2 * b2.z; acc1.w += v2 * b2.w;
            acc0.x += v3 * a3.x; acc0.y += v3 * a3.y; acc0.z += v3 * a3.z; acc0.w += v3 * a3.w;
            acc1.x += v3 * b3.x; acc1.y += v3 * b3.y; acc1.z += v3 * b3.z; acc1.w += v3 * b3.w;
        }
        for (; j < n; j++) {
            int   c = __shfl_sync(0xffffffffu, col, j);
            float v = __shfl_sync(0xffffffffu, val, j);
            const float4* p = reinterpret_cast<const float4*>(g_y + (size_t)c * F_DIM);
            float4 a = __ldg(&p[lane]);
            float4 bb = __ldg(&p[lane + 32]);
            acc0.x += v * a.x;  acc0.y += v * a.y;  acc0.z += v * a.z;  acc0.w += v * a.w;
            acc1.x += v * bb.x; acc1.y += v * bb.y; acc1.z += v * bb.z; acc1.w += v * bb.w;
        }
    }

    const float4* bp = reinterpret_cast<const float4*>(bias);
    float4 bv0 = __ldg(&bp[lane]);
    float4 bv1 = __ldg(&bp[lane + 32]);
    acc0.x += bv0.x; acc0.y += bv0.y; acc0.z += bv0.z; acc0.w += bv0.w;
    acc1.x += bv1.x; acc1.y += bv1.y; acc1.z += bv1.z; acc1.w += bv1.w;

    float4* orow = reinterpret_cast<float4*>(out + (size_t)r * F_DIM);
    orow[lane]      = acc0;
    orow[lane + 32] = acc1;
}

// ---------------------------------------------------------------------------
// Launch
// ---------------------------------------------------------------------------
extern "C" void kernel_launch(void* const* d_in, const int* in_sizes, int n_in,
                              void* d_out, int out_size) {
    const float* x        = (const float*)d_in[0];
    const int*   edge_row = (const int*)  d_in[1];
    const int*   edge_col = (const int*)  d_in[2];
    const float* edge_val = (const float*)d_in[3];
    const float* W        = (const float*)d_in[4];
    const float* b        = (const float*)d_in[5];
    float*       out      = (float*)d_out;

    // zero degree counters (capturable async memset on a __device__ symbol)
    void* cnt_ptr = nullptr;
    cudaGetSymbolAddress(&cnt_ptr, g_cnt);
    cudaMemsetAsync(cnt_ptr, 0, N_NODES * sizeof(int));

    // W split (independent of everything else)
    k_prep_w<<<64, 256>>>(W);

    // CSR build
    k_hist<<<(N_EDGES + 255) / 256, 256>>>(edge_row);
    k_scan1<<<SCAN_NB, SCAN_B>>>();
    k_scan2<<<1, SCAN_B>>>();
    k_scan3<<<SCAN_NB, SCAN_B>>>();
    k_scatter<<<(N_EDGES + 255) / 256, 256>>>(edge_row, edge_col, edge_val);

    // Y = X @ W^T
    dim3 grid(PAD_M / BM, F_DIM / BN);   // 391 x 2
    gemm_kernel<<<grid, 256>>>(x);

    // out = A @ Y + b
    k_gather<<<(N_NODES * 32 + 255) / 256, 256>>>(b, out);
}

// round 5
// speedup vs baseline: 1.7352x; 1.0513x over previous
#include <cuda_runtime.h>
#include <cuda_bf16.h>
#include <cuda_fp16.h>
#include <cstdint>

#define N_NODES   50000
#define F_DIM     256
#define N_EDGES   800000
#define PAD_M     50048          // 391 * 128

#define SCAN_B    256
#define SCAN_NB   ((N_NODES + SCAN_B - 1) / SCAN_B)   // 196

// Scratch (__device__ globals; no allocation allowed)
__device__ __half         g_yh[(size_t)N_NODES * F_DIM];  // Y = X @ W^T in fp16
__device__ __nv_bfloat16  g_w_hi[F_DIM * F_DIM];
__device__ __nv_bfloat16  g_w_lo[F_DIM * F_DIM];
__device__ int   g_cnt[N_NODES];
__device__ int   g_off[N_NODES + 1];
__device__ int   g_pos[N_NODES];
__device__ unsigned long long g_scan_pkt[SCAN_NB];   // decoupled-lookback state
__device__ int   g_col_s[N_EDGES];
__device__ float g_val_s[N_EDGES];

// ---------------------------------------------------------------------------
// W -> (hi, lo) bf16 split
// ---------------------------------------------------------------------------
__device__ __forceinline__ uint32_t pack_bf16_hi(float x, float y) {
    __nv_bfloat162 h = __floats2bfloat162_rn(x, y);
    return *reinterpret_cast<uint32_t*>(&h);
}

__global__ void k_prep_w(const float* __restrict__ W) {
    int i = blockIdx.x * blockDim.x + threadIdx.x;   // float4 index, 16384 total
    float4 v = reinterpret_cast<const float4*>(W)[i];
    uint32_t h0 = pack_bf16_hi(v.x, v.y);
    uint32_t h1 = pack_bf16_hi(v.z, v.w);
    __nv_bfloat162 hb0 = *reinterpret_cast<__nv_bfloat162*>(&h0);
    __nv_bfloat162 hb1 = *reinterpret_cast<__nv_bfloat162*>(&h1);
    uint32_t l0 = pack_bf16_hi(v.x - __bfloat162float(hb0.x),
                               v.y - __bfloat162float(hb0.y));
    uint32_t l1 = pack_bf16_hi(v.z - __bfloat162float(hb1.x),
                               v.w - __bfloat162float(hb1.y));
    uint32_t* whi = reinterpret_cast<uint32_t*>(g_w_hi);
    uint32_t* wlo = reinterpret_cast<uint32_t*>(g_w_lo);
    whi[2 * i]     = h0;
    whi[2 * i + 1] = h1;
    wlo[2 * i]     = l0;
    wlo[2 * i + 1] = l1;
}

// ---------------------------------------------------------------------------
// CSR build: histogram -> single-pass decoupled-lookback scan -> scatter
// ---------------------------------------------------------------------------
__global__ void k_hist(const int* __restrict__ edge_row) {
    int e = blockIdx.x * blockDim.x + threadIdx.x;
    if (e < N_EDGES) atomicAdd(&g_cnt[edge_row[e]], 1);
}

// pkt encoding: bits[62:64) = state (0 invalid, 1 aggregate, 2 prefix); low 32 = value
__global__ void k_scan_fused() {
    __shared__ int warp_sums[8];
    __shared__ int s_base;
    const int b    = blockIdx.x;
    const int t    = threadIdx.x;
    const int lane = t & 31;
    const int w    = t >> 5;
    const int i    = b * SCAN_B + t;

    int v = (i < N_NODES) ? g_cnt[i] : 0;

    // warp inclusive scan
    int inc = v;
#pragma unroll
    for (int d = 1; d < 32; d <<= 1) {
        int tt = __shfl_up_sync(0xffffffffu, inc, d);
        if (lane >= d) inc += tt;
    }
    if (lane == 31) warp_sums[w] = inc;
    __syncthreads();
    if (w == 0) {
        int ws = (lane < 8) ? warp_sums[lane] : 0;
#pragma unroll
        for (int d = 1; d < 8; d <<= 1) {
            int tt = __shfl_up_sync(0xffffffffu, ws, d);
            if (lane >= d) ws += tt;
        }
        if (lane < 8) warp_sums[lane] = ws;     // inclusive warp prefix
    }
    __syncthreads();
    int excl  = inc - v + ((w > 0) ? warp_sums[w - 1] : 0);
    int total = warp_sums[7];

    if (t == 0) {
        if (b == 0) {
            atomicExch(&g_scan_pkt[0], (2ULL << 62) | (unsigned)total);
            s_base = 0;
        } else {
            atomicExch(&g_scan_pkt[b], (1ULL << 62) | (unsigned)total);
            int run = 0;
            int j = b - 1;
            while (true) {
                unsigned long long p;
                while (((p = atomicAdd(&g_scan_pkt[j], 0ULL)) >> 62) == 0) {}
                run += (int)(p & 0xFFFFFFFFULL);
                if ((p >> 62) == 2ULL) break;
                j--;
            }
            atomicExch(&g_scan_pkt[b], (2ULL << 62) | (unsigned)(run + total));
            s_base = run;
        }
    }
    __syncthreads();
    int base = s_base;
    if (i < N_NODES) {
        int o = base + excl;
        g_off[i] = o;
        g_pos[i] = o;
    }
    if (i == N_NODES - 1) g_off[N_NODES] = N_EDGES;
}

__global__ void k_scatter(const int*   __restrict__ edge_row,
                          const int*   __restrict__ edge_col,
                          const float* __restrict__ edge_val) {
    int e = blockIdx.x * blockDim.x + threadIdx.x;
    if (e < N_EDGES) {
        int r = edge_row[e];
        int p = atomicAdd(&g_pos[r], 1);
        g_col_s[p] = edge_col[e];
        g_val_s[p] = edge_val[e];
    }
}

// ---------------------------------------------------------------------------
// GEMM  Y[m,n] = sum_k X[m,k]*W[n,k]  (split-bf16, 3 MMAs), Y stored fp16
// ---------------------------------------------------------------------------
#define BM 128
#define BN 128
#define BK 32
#define LDS_K 40

__device__ __forceinline__ void mma_bf16(float* c, const uint32_t* a, const uint32_t* b) {
    asm volatile(
        "mma.sync.aligned.m16n8k16.row.col.f32.bf16.bf16.f32 "
        "{%0,%1,%2,%3}, {%4,%5,%6,%7}, {%8,%9}, {%0,%1,%2,%3};"
        : "+f"(c[0]), "+f"(c[1]), "+f"(c[2]), "+f"(c[3])
        : "r"(a[0]), "r"(a[1]), "r"(a[2]), "r"(a[3]), "r"(b[0]), "r"(b[1]));
}

__global__ __launch_bounds__(256, 1)
void gemm_kernel(const float* __restrict__ X) {
    __shared__ __nv_bfloat16 As_hi[BM][LDS_K];
    __shared__ __nv_bfloat16 As_lo[BM][LDS_K];
    __shared__ __nv_bfloat16 Ws_hi[BN][LDS_K];
    __shared__ __nv_bfloat16 Ws_lo[BN][LDS_K];

    const int t    = threadIdx.x;
    const int lane = t & 31;
    const int wid  = t >> 5;
    const int wm   = wid & 3;
    const int wn   = wid >> 2;
    const int g    = lane >> 2;
    const int tid4 = lane & 3;

    const int m0 = blockIdx.x * BM;
    const int n0 = blockIdx.y * BN;

    float acc[2][8][4];
#pragma unroll
    for (int i = 0; i < 2; i++)
#pragma unroll
        for (int j = 0; j < 8; j++)
#pragma unroll
            for (int k = 0; k < 4; k++) acc[i][j][k] = 0.f;

    for (int k0 = 0; k0 < F_DIM; k0 += BK) {
#pragma unroll
        for (int i = 0; i < 4; i++) {
            int idx = t + i * 256;
            int row = idx >> 3;
            int c4  = idx & 7;
            int m   = m0 + row;
            float4 v = make_float4(0.f, 0.f, 0.f, 0.f);
            if (m < N_NODES)
                v = *reinterpret_cast<const float4*>(X + (size_t)m * F_DIM + k0 + c4 * 4);
            uint32_t h0 = pack_bf16_hi(v.x, v.y);
            uint32_t h1 = pack_bf16_hi(v.z, v.w);
            __nv_bfloat162 hb0 = *reinterpret_cast<__nv_bfloat162*>(&h0);
            __nv_bfloat162 hb1 = *reinterpret_cast<__nv_bfloat162*>(&h1);
            uint32_t l0 = pack_bf16_hi(v.x - __bfloat162float(hb0.x),
                                       v.y - __bfloat162float(hb0.y));
            uint32_t l1 = pack_bf16_hi(v.z - __bfloat162float(hb1.x),
                                       v.w - __bfloat162float(hb1.y));
            *reinterpret_cast<uint32_t*>(&As_hi[row][c4 * 4])     = h0;
            *reinterpret_cast<uint32_t*>(&As_hi[row][c4 * 4 + 2]) = h1;
            *reinterpret_cast<uint32_t*>(&As_lo[row][c4 * 4])     = l0;
            *reinterpret_cast<uint32_t*>(&As_lo[row][c4 * 4 + 2]) = l1;
        }
#pragma unroll
        for (int i = 0; i < 2; i++) {
            int idx = t + i * 256;
            int row = idx >> 2;
            int c8  = idx & 3;
            size_t goff = (size_t)(n0 + row) * F_DIM + k0 + c8 * 8;
            uint4 vh = *reinterpret_cast<const uint4*>(g_w_hi + goff);
            uint4 vl = *reinterpret_cast<const uint4*>(g_w_lo + goff);
            *reinterpret_cast<uint4*>(&Ws_hi[row][c8 * 8]) = vh;
            *reinterpret_cast<uint4*>(&Ws_lo[row][c8 * 8]) = vl;
        }
        __syncthreads();

#pragma unroll
        for (int ks = 0; ks < 2; ks++) {
            int kb = ks * 16;
            uint32_t a_hi[2][4], a_lo[2][4];
#pragma unroll
            for (int mi = 0; mi < 2; mi++) {
                int r = wm * 32 + mi * 16;
                a_hi[mi][0] = *reinterpret_cast<const uint32_t*>(&As_hi[r + g    ][kb + 2 * tid4]);
                a_hi[mi][1] = *reinterpret_cast<const uint32_t*>(&As_hi[r + g + 8][kb + 2 * tid4]);
                a_hi[mi][2] = *reinterpret_cast<const uint32_t*>(&As_hi[r + g    ][kb + 2 * tid4 + 8]);
                a_hi[mi][3] = *reinterpret_cast<const uint32_t*>(&As_hi[r + g + 8][kb + 2 * tid4 + 8]);
                a_lo[mi][0] = *reinterpret_cast<const uint32_t*>(&As_lo[r + g    ][kb + 2 * tid4]);
                a_lo[mi][1] = *reinterpret_cast<const uint32_t*>(&As_lo[r + g + 8][kb + 2 * tid4]);
                a_lo[mi][2] = *reinterpret_cast<const uint32_t*>(&As_lo[r + g    ][kb + 2 * tid4 + 8]);
                a_lo[mi][3] = *reinterpret_cast<const uint32_t*>(&As_lo[r + g + 8][kb + 2 * tid4 + 8]);
            }
            uint32_t b_hi[8][2], b_lo[8][2];
#pragma unroll
            for (int ni = 0; ni < 8; ni++) {
                int n = wn * 64 + ni * 8 + g;
                b_hi[ni][0] = *reinterpret_cast<const uint32_t*>(&Ws_hi[n][kb + 2 * tid4]);
                b_hi[ni][1] = *reinterpret_cast<const uint32_t*>(&Ws_hi[n][kb + 2 * tid4 + 8]);
                b_lo[ni][0] = *reinterpret_cast<const uint32_t*>(&Ws_lo[n][kb + 2 * tid4]);
                b_lo[ni][1] = *reinterpret_cast<const uint32_t*>(&Ws_lo[n][kb + 2 * tid4 + 8]);
            }
#pragma unroll
            for (int mi = 0; mi < 2; mi++) {
#pragma unroll
                for (int ni = 0; ni < 8; ni++) {
                    mma_bf16(acc[mi][ni], a_hi[mi], b_hi[ni]);
                    mma_bf16(acc[mi][ni], a_hi[mi], b_lo[ni]);
                    mma_bf16(acc[mi][ni], a_lo[mi], b_hi[ni]);
                }
            }
        }
        __syncthreads();
    }

    // ---- store Y as fp16 (half2 per acc pair)
#pragma unroll
    for (int mi = 0; mi < 2; mi++) {
        int r_base = m0 + wm * 32 + mi * 16;
#pragma unroll
        for (int ni = 0; ni < 8; ni++) {
            int col = n0 + wn * 64 + ni * 8 + 2 * tid4;
            int r0 = r_base + g;
            int r1 = r_base + g + 8;
            if (r0 < N_NODES) {
                __half2 h = __floats2half2_rn(acc[mi][ni][0], acc[mi][ni][1]);
                *reinterpret_cast<__half2*>(g_yh + (size_t)r0 * F_DIM + col) = h;
            }
            if (r1 < N_NODES) {
                __half2 h = __floats2half2_rn(acc[mi][ni][2], acc[mi][ni][3]);
                *reinterpret_cast<__half2*>(g_yh + (size_t)r1 * F_DIM + col) = h;
            }
        }
    }
}

// ---------------------------------------------------------------------------
// Gather: out[r] = sum_e val_e * Y[col_e] + b.  One warp per row.
// Y is fp16: each lane covers 8 features (one uint4 load per edge).
// ---------------------------------------------------------------------------
__device__ __forceinline__ void fma8(float* acc, uint4 u, float v) {
    const __half2* h = reinterpret_cast<const __half2*>(&u);
#pragma unroll
    for (int q = 0; q < 4; q++) {
        float2 f = __half22float2(h[q]);
        acc[2 * q]     += v * f.x;
        acc[2 * q + 1] += v * f.y;
    }
}

__global__ __launch_bounds__(256)
void k_gather(const float* __restrict__ bias, float* __restrict__ out) {
    int r    = (blockIdx.x * blockDim.x + threadIdx.x) >> 5;
    int lane = threadIdx.x & 31;
    if (r >= N_NODES) return;

    float acc[8];
#pragma unroll
    for (int q = 0; q < 8; q++) acc[q] = 0.f;

    int start = g_off[r];
    int end   = g_off[r + 1];

    for (int base = start; base < end; base += 32) {
        int n = min(32, end - base);
        int   col = 0;
        float val = 0.f;
        if (lane < n) {
            col = g_col_s[base + lane];
            val = g_val_s[base + lane];
        }
        int j = 0;
        for (; j + 4 <= n; j += 4) {
            int   c0 = __shfl_sync(0xffffffffu, col, j);
            int   c1 = __shfl_sync(0xffffffffu, col, j + 1);
            int   c2 = __shfl_sync(0xffffffffu, col, j + 2);
            int   c3 = __shfl_sync(0xffffffffu, col, j + 3);
            float v0 = __shfl_sync(0xffffffffu, val, j);
            float v1 = __shfl_sync(0xffffffffu, val, j + 1);
            float v2 = __shfl_sync(0xffffffffu, val, j + 2);
            float v3 = __shfl_sync(0xffffffffu, val, j + 3);
            uint4 u0 = __ldg(reinterpret_cast<const uint4*>(g_yh + (size_t)c0 * F_DIM) + lane);
            uint4 u1 = __ldg(reinterpret_cast<const uint4*>(g_yh + (size_t)c1 * F_DIM) + lane);
            uint4 u2 = __ldg(reinterpret_cast<const uint4*>(g_yh + (size_t)c2 * F_DIM) + lane);
            uint4 u3 = __ldg(reinterpret_cast<const uint4*>(g_yh + (size_t)c3 * F_DIM) + lane);
            fma8(acc, u0, v0);
            fma8(acc, u1, v1);
            fma8(acc, u2, v2);
            fma8(acc, u3, v3);
        }
        for (; j < n; j++) {
            int   c = __shfl_sync(0xffffffffu, col, j);
            float v = __shfl_sync(0xffffffffu, val, j);
            uint4 u = __ldg(reinterpret_cast<const uint4*>(g_yh + (size_t)c * F_DIM) + lane);
            fma8(acc, u, v);
        }
    }

    // bias + store: lane covers features lane*8 .. lane*8+7
    const float4* bp = reinterpret_cast<const float4*>(bias + lane * 8);
    float4 b0 = __ldg(bp);
    float4 b1 = __ldg(bp + 1);
    float4 o0 = make_float4(acc[0] + b0.x, acc[1] + b0.y, acc[2] + b0.z, acc[3] + b0.w);
    float4 o1 = make_float4(acc[4] + b1.x, acc[5] + b1.y, acc[6] + b1.z, acc[7] + b1.w);
    float4* orow = reinterpret_cast<float4*>(out + (size_t)r * F_DIM + lane * 8);
    orow[0] = o0;
    orow[1] = o1;
}

// ---------------------------------------------------------------------------
// Launch
// ---------------------------------------------------------------------------
extern "C" void kernel_launch(void* const* d_in, const int* in_sizes, int n_in,
                              void* d_out, int out_size) {
    const float* x        = (const float*)d_in[0];
    const int*   edge_row = (const int*)  d_in[1];
    const int*   edge_col = (const int*)  d_in[2];
    const float* edge_val = (const float*)d_in[3];
    const float* W        = (const float*)d_in[4];
    const float* b        = (const float*)d_in[5];
    float*       out      = (float*)d_out;

    void* cnt_ptr = nullptr;
    cudaGetSymbolAddress(&cnt_ptr, g_cnt);
    cudaMemsetAsync(cnt_ptr, 0, N_NODES * sizeof(int));
    void* pkt_ptr = nullptr;
    cudaGetSymbolAddress(&pkt_ptr, g_scan_pkt);
    cudaMemsetAsync(pkt_ptr, 0, SCAN_NB * sizeof(unsigned long long));

    k_prep_w<<<64, 256>>>(W);
    k_hist<<<(N_EDGES + 255) / 256, 256>>>(edge_row);
    k_scan_fused<<<SCAN_NB, SCAN_B>>>();
    k_scatter<<<(N_EDGES + 255) / 256, 256>>>(edge_row, edge_col, edge_val);

    dim3 grid(PAD_M / BM, F_DIM / BN);   // 391 x 2
    gemm_kernel<<<grid, 256>>>(x);

    k_gather<<<(N_NODES * 32 + 255) / 256, 256>>>(b, out);
}

// round 6
// speedup vs baseline: 2.4499x; 1.4119x over previous
#include <cuda_runtime.h>
#include <cuda_fp16.h>
#include <cstdint>

#define N_NODES   50000
#define F_DIM     256
#define N_EDGES   800000
#define PAD_M     50048          // 391 * 128

#define SCAN_B    256
#define SCAN_NB   ((N_NODES + SCAN_B - 1) / SCAN_B)   // 196

// Scratch (__device__ globals; no allocation allowed)
__device__ __half g_yh[(size_t)N_NODES * F_DIM];  // Y = X @ W^T, fp16
__device__ __half g_wh[F_DIM * F_DIM];            // W in fp16
__device__ int    g_cnt[N_NODES];
__device__ int    g_off[N_NODES + 1];
__device__ int    g_pos[N_NODES];
__device__ unsigned long long g_scan_pkt[SCAN_NB];
__device__ int2   g_cv[N_EDGES];                  // packed (col, val-bits)

// ---------------------------------------------------------------------------
// W -> fp16
// ---------------------------------------------------------------------------
__global__ void k_prep_w(const float* __restrict__ W) {
    int i = blockIdx.x * blockDim.x + threadIdx.x;   // float4 index, 16384 total
    float4 v = reinterpret_cast<const float4*>(W)[i];
    __half2 h0 = __floats2half2_rn(v.x, v.y);
    __half2 h1 = __floats2half2_rn(v.z, v.w);
    reinterpret_cast<__half2*>(g_wh)[2 * i]     = h0;
    reinterpret_cast<__half2*>(g_wh)[2 * i + 1] = h1;
}

// ---------------------------------------------------------------------------
// CSR build: histogram -> single-pass decoupled-lookback scan -> packed scatter
// ---------------------------------------------------------------------------
__global__ void k_hist(const int* __restrict__ edge_row) {
    int e = blockIdx.x * blockDim.x + threadIdx.x;
    if (e < N_EDGES) atomicAdd(&g_cnt[edge_row[e]], 1);
}

// pkt encoding: bits[62:64) = state (0 invalid, 1 aggregate, 2 prefix); low 32 = value
__global__ void k_scan_fused() {
    __shared__ int warp_sums[8];
    __shared__ int s_base;
    const int b    = blockIdx.x;
    const int t    = threadIdx.x;
    const int lane = t & 31;
    const int w    = t >> 5;
    const int i    = b * SCAN_B + t;

    int v = (i < N_NODES) ? g_cnt[i] : 0;

    int inc = v;
#pragma unroll
    for (int d = 1; d < 32; d <<= 1) {
        int tt = __shfl_up_sync(0xffffffffu, inc, d);
        if (lane >= d) inc += tt;
    }
    if (lane == 31) warp_sums[w] = inc;
    __syncthreads();
    if (w == 0) {
        int ws = (lane < 8) ? warp_sums[lane] : 0;
#pragma unroll
        for (int d = 1; d < 8; d <<= 1) {
            int tt = __shfl_up_sync(0xffffffffu, ws, d);
            if (lane >= d) ws += tt;
        }
        if (lane < 8) warp_sums[lane] = ws;
    }
    __syncthreads();
    int excl  = inc - v + ((w > 0) ? warp_sums[w - 1] : 0);
    int total = warp_sums[7];

    if (t == 0) {
        if (b == 0) {
            atomicExch(&g_scan_pkt[0], (2ULL << 62) | (unsigned)total);
            s_base = 0;
        } else {
            atomicExch(&g_scan_pkt[b], (1ULL << 62) | (unsigned)total);
            int run = 0;
            int j = b - 1;
            while (true) {
                unsigned long long p;
                while (((p = atomicAdd(&g_scan_pkt[j], 0ULL)) >> 62) == 0) {}
                run += (int)(p & 0xFFFFFFFFULL);
                if ((p >> 62) == 2ULL) break;
                j--;
            }
            atomicExch(&g_scan_pkt[b], (2ULL << 62) | (unsigned)(run + total));
            s_base = run;
        }
    }
    __syncthreads();
    int base = s_base;
    if (i < N_NODES) {
        int o = base + excl;
        g_off[i] = o;
        g_pos[i] = o;
    }
    if (i == N_NODES - 1) g_off[N_NODES] = N_EDGES;
}

__global__ void k_scatter(const int*   __restrict__ edge_row,
                          const int*   __restrict__ edge_col,
                          const float* __restrict__ edge_val) {
    int e = blockIdx.x * blockDim.x + threadIdx.x;
    if (e < N_EDGES) {
        int r = edge_row[e];
        int p = atomicAdd(&g_pos[r], 1);
        g_cv[p] = make_int2(edge_col[e], __float_as_int(edge_val[e]));
    }
}

// ---------------------------------------------------------------------------
// GEMM  Y[m,n] = sum_k X[m,k]*W[n,k]   -- plain fp16 MMA, fp32 accumulate
// CTA 128x128, BK=32, 8 warps 4(M) x 2(N).
// ---------------------------------------------------------------------------
#define BM 128
#define BN 128
#define BK 32
#define LDS_K 40

__device__ __forceinline__ void mma_f16(float* c, const uint32_t* a, const uint32_t* b) {
    asm volatile(
        "mma.sync.aligned.m16n8k16.row.col.f32.f16.f16.f32 "
        "{%0,%1,%2,%3}, {%4,%5,%6,%7}, {%8,%9}, {%0,%1,%2,%3};"
        : "+f"(c[0]), "+f"(c[1]), "+f"(c[2]), "+f"(c[3])
        : "r"(a[0]), "r"(a[1]), "r"(a[2]), "r"(a[3]), "r"(b[0]), "r"(b[1]));
}

__global__ __launch_bounds__(256, 2)
void gemm_kernel(const float* __restrict__ X) {
    __shared__ __half As[BM][LDS_K];
    __shared__ __half Ws[BN][LDS_K];

    const int t    = threadIdx.x;
    const int lane = t & 31;
    const int wid  = t >> 5;
    const int wm   = wid & 3;
    const int wn   = wid >> 2;
    const int g    = lane >> 2;
    const int tid4 = lane & 3;

    const int m0 = blockIdx.x * BM;
    const int n0 = blockIdx.y * BN;

    float acc[2][8][4];
#pragma unroll
    for (int i = 0; i < 2; i++)
#pragma unroll
        for (int j = 0; j < 8; j++)
#pragma unroll
            for (int k = 0; k < 4; k++) acc[i][j][k] = 0.f;

    for (int k0 = 0; k0 < F_DIM; k0 += BK) {
        // ---- stage X tile (fp32 -> fp16), rows >= N_NODES zero-filled
#pragma unroll
        for (int i = 0; i < 4; i++) {
            int idx = t + i * 256;       // 0..1023
            int row = idx >> 3;          // 0..127
            int c4  = idx & 7;           // 0..7 (4 floats each)
            int m   = m0 + row;
            float4 v = make_float4(0.f, 0.f, 0.f, 0.f);
            if (m < N_NODES)
                v = *reinterpret_cast<const float4*>(X + (size_t)m * F_DIM + k0 + c4 * 4);
            __half2 h0 = __floats2half2_rn(v.x, v.y);
            __half2 h1 = __floats2half2_rn(v.z, v.w);
            uint2 u;
            u.x = *reinterpret_cast<uint32_t*>(&h0);
            u.y = *reinterpret_cast<uint32_t*>(&h1);
            *reinterpret_cast<uint2*>(&As[row][c4 * 4]) = u;
        }
        // ---- stage W tile: straight 16B copies of pre-converted fp16
#pragma unroll
        for (int i = 0; i < 2; i++) {
            int idx = t + i * 256;       // 0..511
            int row = idx >> 2;          // 0..127
            int c8  = idx & 3;           // chunks of 8 halfs
            size_t goff = (size_t)(n0 + row) * F_DIM + k0 + c8 * 8;
            uint4 vh = *reinterpret_cast<const uint4*>(g_wh + goff);
            *reinterpret_cast<uint4*>(&Ws[row][c8 * 8]) = vh;
        }
        __syncthreads();

#pragma unroll
        for (int ks = 0; ks < 2; ks++) {
            int kb = ks * 16;
            uint32_t a[2][4];
#pragma unroll
            for (int mi = 0; mi < 2; mi++) {
                int r = wm * 32 + mi * 16;
                a[mi][0] = *reinterpret_cast<const uint32_t*>(&As[r + g    ][kb + 2 * tid4]);
                a[mi][1] = *reinterpret_cast<const uint32_t*>(&As[r + g + 8][kb + 2 * tid4]);
                a[mi][2] = *reinterpret_cast<const uint32_t*>(&As[r + g    ][kb + 2 * tid4 + 8]);
                a[mi][3] = *reinterpret_cast<const uint32_t*>(&As[r + g + 8][kb + 2 * tid4 + 8]);
            }
            uint32_t b[8][2];
#pragma unroll
            for (int ni = 0; ni < 8; ni++) {
                int n = wn * 64 + ni * 8 + g;
                b[ni][0] = *reinterpret_cast<const uint32_t*>(&Ws[n][kb + 2 * tid4]);
                b[ni][1] = *reinterpret_cast<const uint32_t*>(&Ws[n][kb + 2 * tid4 + 8]);
            }
#pragma unroll
            for (int mi = 0; mi < 2; mi++)
#pragma unroll
                for (int ni = 0; ni < 8; ni++)
                    mma_f16(acc[mi][ni], a[mi], b[ni]);
        }
        __syncthreads();
    }

    // ---- store Y as fp16
#pragma unroll
    for (int mi = 0; mi < 2; mi++) {
        int r_base = m0 + wm * 32 + mi * 16;
#pragma unroll
        for (int ni = 0; ni < 8; ni++) {
            int col = n0 + wn * 64 + ni * 8 + 2 * tid4;
            int r0 = r_base + g;
            int r1 = r_base + g + 8;
            if (r0 < N_NODES) {
                __half2 h = __floats2half2_rn(acc[mi][ni][0], acc[mi][ni][1]);
                *reinterpret_cast<__half2*>(g_yh + (size_t)r0 * F_DIM + col) = h;
            }
            if (r1 < N_NODES) {
                __half2 h = __floats2half2_rn(acc[mi][ni][2], acc[mi][ni][3]);
                *reinterpret_cast<__half2*>(g_yh + (size_t)r1 * F_DIM + col) = h;
            }
        }
    }
}

// ---------------------------------------------------------------------------
// Gather: out[r] = sum_e val_e * Y[col_e] + b.  One warp per row.
// Y fp16: lane covers 8 features (one uint4 load per edge).
// ---------------------------------------------------------------------------
__device__ __forceinline__ void fma8(float* acc, uint4 u, float v) {
    const __half2* h = reinterpret_cast<const __half2*>(&u);
#pragma unroll
    for (int q = 0; q < 4; q++) {
        float2 f = __half22float2(h[q]);
        acc[2 * q]     += v * f.x;
        acc[2 * q + 1] += v * f.y;
    }
}

__global__ __launch_bounds__(256)
void k_gather(const float* __restrict__ bias, float* __restrict__ out) {
    int r    = (blockIdx.x * blockDim.x + threadIdx.x) >> 5;
    int lane = threadIdx.x & 31;
    if (r >= N_NODES) return;

    float acc[8];
#pragma unroll
    for (int q = 0; q < 8; q++) acc[q] = 0.f;

    int start = g_off[r];
    int end   = g_off[r + 1];

    for (int base = start; base < end; base += 32) {
        int n = min(32, end - base);
        int   col = 0;
        float val = 0.f;
        if (lane < n) {
            int2 cv = __ldg(&g_cv[base + lane]);
            col = cv.x;
            val = __int_as_float(cv.y);
        }
        int j = 0;
        for (; j + 4 <= n; j += 4) {
            int   c0 = __shfl_sync(0xffffffffu, col, j);
            int   c1 = __shfl_sync(0xffffffffu, col, j + 1);
            int   c2 = __shfl_sync(0xffffffffu, col, j + 2);
            int   c3 = __shfl_sync(0xffffffffu, col, j + 3);
            float v0 = __shfl_sync(0xffffffffu, val, j);
            float v1 = __shfl_sync(0xffffffffu, val, j + 1);
            float v2 = __shfl_sync(0xffffffffu, val, j + 2);
            float v3 = __shfl_sync(0xffffffffu, val, j + 3);
            uint4 u0 = __ldg(reinterpret_cast<const uint4*>(g_yh + (size_t)c0 * F_DIM) + lane);
            uint4 u1 = __ldg(reinterpret_cast<const uint4*>(g_yh + (size_t)c1 * F_DIM) + lane);
            uint4 u2 = __ldg(reinterpret_cast<const uint4*>(g_yh + (size_t)c2 * F_DIM) + lane);
            uint4 u3 = __ldg(reinterpret_cast<const uint4*>(g_yh + (size_t)c3 * F_DIM) + lane);
            fma8(acc, u0, v0);
            fma8(acc, u1, v1);
            fma8(acc, u2, v2);
            fma8(acc, u3, v3);
        }
        for (; j < n; j++) {
            int   c = __shfl_sync(0xffffffffu, col, j);
            float v = __shfl_sync(0xffffffffu, val, j);
            uint4 u = __ldg(reinterpret_cast<const uint4*>(g_yh + (size_t)c * F_DIM) + lane);
            fma8(acc, u, v);
        }
    }

    const float4* bp = reinterpret_cast<const float4*>(bias + lane * 8);
    float4 b0 = __ldg(bp);
    float4 b1 = __ldg(bp + 1);
    float4 o0 = make_float4(acc[0] + b0.x, acc[1] + b0.y, acc[2] + b0.z, acc[3] + b0.w);
    float4 o1 = make_float4(acc[4] + b1.x, acc[5] + b1.y, acc[6] + b1.z, acc[7] + b1.w);
    float4* orow = reinterpret_cast<float4*>(out + (size_t)r * F_DIM + lane * 8);
    orow[0] = o0;
    orow[1] = o1;
}

// ---------------------------------------------------------------------------
// Launch
// ---------------------------------------------------------------------------
extern "C" void kernel_launch(void* const* d_in, const int* in_sizes, int n_in,
                              void* d_out, int out_size) {
    const float* x        = (const float*)d_in[0];
    const int*   edge_row = (const int*)  d_in[1];
    const int*   edge_col = (const int*)  d_in[2];
    const float* edge_val = (const float*)d_in[3];
    const float* W        = (const float*)d_in[4];
    const float* b        = (const float*)d_in[5];
    float*       out      = (float*)d_out;

    void* cnt_ptr = nullptr;
    cudaGetSymbolAddress(&cnt_ptr, g_cnt);
    cudaMemsetAsync(cnt_ptr, 0, N_NODES * sizeof(int));
    void* pkt_ptr = nullptr;
    cudaGetSymbolAddress(&pkt_ptr, g_scan_pkt);
    cudaMemsetAsync(pkt_ptr, 0, SCAN_NB * sizeof(unsigned long long));

    k_prep_w<<<64, 256>>>(W);
    k_hist<<<(N_EDGES + 255) / 256, 256>>>(edge_row);
    k_scan_fused<<<SCAN_NB, SCAN_B>>>();
    k_scatter<<<(N_EDGES + 255) / 256, 256>>>(edge_row, edge_col, edge_val);

    dim3 grid(PAD_M / BM, F_DIM / BN);   // 391 x 2
    gemm_kernel<<<grid, 256>>>(x);

    k_gather<<<(N_NODES * 32 + 255) / 256, 256>>>(b, out);
}